// round 2
// baseline (speedup 1.0000x reference)
#include <cuda_runtime.h>
#include <math.h>
#include <float.h>

// Problem constants
#define BATCH   256
#define NLEV    4
#define CDIM    8000
#define NTOTAL  10500

__constant__ int c_sizes[4] = {100, 400, 2000, 8000};

// Scratch (allocation-free requirement): per (b, level) nll and argmax.
__device__ float g_nll[BATCH * NLEV];
__device__ int   g_amax[BATCH * NLEV];

__device__ __forceinline__ void combine(float& m, float& s, float& av, int& ai,
                                        float m2, float s2, float av2, int ai2) {
    float nm = fmaxf(m, m2);
    s = s * __expf(m - nm) + s2 * __expf(m2 - nm);
    m = nm;
    // argmax: prefer larger value; on exact tie prefer smaller index (jnp.argmax semantics)
    if (av2 > av || (av2 == av && ai2 < ai)) { av = av2; ai = ai2; }
}

// Kernel 1: one block per (b, level). Online softmax + argmax over valid prefix.
__global__ void __launch_bounds__(256) level_reduce_kernel(
    const float* __restrict__ y_pred,
    const int* __restrict__ y_true)     // int32: JAX downcasts int64 without x64
{
    const int bj = blockIdx.x;
    const int b  = bj >> 2;
    const int j  = bj & 3;
    const int n  = c_sizes[j];

    const float* row = y_pred + ((size_t)b * NLEV + j) * CDIM;

    float m  = -FLT_MAX;
    float s  = 0.0f;
    float av = -FLT_MAX;
    int   ai = 0x7fffffff;

    // n is divisible by 4 for all levels; float4 strided loop.
    const int n4 = n >> 2;
    const float4* row4 = reinterpret_cast<const float4*>(row);
    for (int i4 = threadIdx.x; i4 < n4; i4 += blockDim.x) {
        float4 v4 = row4[i4];
        float vs[4] = {v4.x, v4.y, v4.z, v4.w};
        #pragma unroll
        for (int k = 0; k < 4; k++) {
            float v = vs[k];
            float nm = fmaxf(m, v);
            s = s * __expf(m - nm) + __expf(v - nm);
            m = nm;
            if (v > av) { av = v; ai = i4 * 4 + k; }   // strictly > keeps first index
        }
    }

    // Warp reduce
    #pragma unroll
    for (int off = 16; off > 0; off >>= 1) {
        float m2  = __shfl_down_sync(0xffffffffu, m,  off);
        float s2  = __shfl_down_sync(0xffffffffu, s,  off);
        float av2 = __shfl_down_sync(0xffffffffu, av, off);
        int   ai2 = __shfl_down_sync(0xffffffffu, ai, off);
        combine(m, s, av, ai, m2, s2, av2, ai2);
    }

    __shared__ float sm[8], ss[8], sav[8];
    __shared__ int   sai[8];
    const int lane = threadIdx.x & 31;
    const int warp = threadIdx.x >> 5;
    if (lane == 0) { sm[warp] = m; ss[warp] = s; sav[warp] = av; sai[warp] = ai; }
    __syncthreads();

    if (warp == 0) {
        if (lane < 8) { m = sm[lane]; s = ss[lane]; av = sav[lane]; ai = sai[lane]; }
        else          { m = -FLT_MAX; s = 0.0f; av = -FLT_MAX; ai = 0x7fffffff; }
        #pragma unroll
        for (int off = 4; off > 0; off >>= 1) {
            float m2  = __shfl_down_sync(0xffffffffu, m,  off);
            float s2  = __shfl_down_sync(0xffffffffu, s,  off);
            float av2 = __shfl_down_sync(0xffffffffu, av, off);
            int   ai2 = __shfl_down_sync(0xffffffffu, ai, off);
            combine(m, s, av, ai, m2, s2, av2, ai2);
        }
        if (lane == 0) {
            int tgt = y_true[b * NLEV + j];
            // Defensive clamp: correct targets are already in [0, n); this only
            // prevents an OOB crash from hiding a dtype mismatch signal.
            tgt = min(max(tgt, 0), n - 1);
            float logit_t = row[tgt];
            // nll = logsumexp - logit_t = (m + log(s)) - logit_t
            g_nll[bj]  = m + logf(s) - logit_t;
            g_amax[bj] = ai;
        }
    }
}

// Kernel 2: final scalar. One block, thread b handles row b.
__global__ void __launch_bounds__(256) finalize_kernel(
    const float* __restrict__ H,
    float* __restrict__ out)
{
    const int b = threadIdx.x;

    int g0 = g_amax[b * 4 + 0] + 0;
    int g1 = g_amax[b * 4 + 1] + 100;
    int g2 = g_amax[b * 4 + 2] + 500;
    int g3 = g_amax[b * 4 + 3] + 2500;

    const float E = 2.7182817459106445f;   // float32(np.e)
    const float invB = 1.0f / (float)BATCH;

    float c01 = (H[(size_t)g0 * NTOTAL + g1] == 1.0f) ? 1.0f : 0.0f;
    float c12 = (H[(size_t)g1 * NTOTAL + g2] == 1.0f) ? 1.0f : 0.0f;
    float c23 = (H[(size_t)g2 * NTOTAL + g3] == 1.0f) ? 1.0f : 0.0f;

    float part = 0.0f;
    part += 0.25f * (E * c01 + g_nll[b * 4 + 1] * invB);
    part += 0.15f * (E * c12 + g_nll[b * 4 + 2] * invB);
    part += 0.10f * (E * c23 + g_nll[b * 4 + 3] * invB);

    // Block tree reduce
    __shared__ float sh[256];
    sh[b] = part;
    __syncthreads();
    #pragma unroll
    for (int off = 128; off > 0; off >>= 1) {
        if (b < off) sh[b] += sh[b + off];
        __syncthreads();
    }
    if (b == 0) out[0] = sh[0];
}

extern "C" void kernel_launch(void* const* d_in, const int* in_sizes, int n_in,
                              void* d_out, int out_size) {
    const float* y_pred = (const float*)d_in[0];
    const int*   y_true = (const int*)d_in[1];
    const float* H      = (const float*)d_in[2];
    float*       out    = (float*)d_out;

    level_reduce_kernel<<<BATCH * NLEV, 256>>>(y_pred, y_true);
    finalize_kernel<<<1, 256>>>(H, out);
}

// round 3
// speedup vs baseline: 1.1830x; 1.1830x over previous
#include <cuda_runtime.h>
#include <math.h>
#include <float.h>

#define BATCH   256
#define NLEV    4
#define CDIM    8000
#define NTOTAL  10500

// Scratch (allocation-free): per-block partial + completion counter.
__device__ float        g_part[BATCH];
__device__ unsigned int g_count = 0;

__device__ __forceinline__ void comb(float& m, float& s, float& av, int& ai,
                                     float m2, float s2, float av2, int ai2) {
    float nm = fmaxf(m, m2);
    s = s * __expf(m - nm) + s2 * __expf(m2 - nm);
    m = nm;
    // argmax: larger value wins; on tie smaller index (jnp.argmax first-max)
    if (av2 > av || (av2 == av && ai2 < ai)) { av = av2; ai = ai2; }
}

// Per-thread accumulation over one level's valid prefix, 4 independent lane
// accumulators (one per float4 component) to break the exp-rescale chain.
__device__ __forceinline__ void accum_level(const float4* __restrict__ row4, int n4,
                                            float& m, float& s, float& av, int& ai) {
    float m0 = -FLT_MAX, m1 = -FLT_MAX, m2 = -FLT_MAX, m3 = -FLT_MAX;
    float s0 = 0.f, s1 = 0.f, s2 = 0.f, s3 = 0.f;
    float a0 = -FLT_MAX, a1 = -FLT_MAX, a2 = -FLT_MAX, a3 = -FLT_MAX;
    int   i0 = 0x7fffffff, i1 = 0x7fffffff, i2 = 0x7fffffff, i3 = 0x7fffffff;

    for (int i4 = threadIdx.x; i4 < n4; i4 += 256) {
        float4 v = __ldg(&row4[i4]);
        { float nm = fmaxf(m0, v.x); s0 = s0 * __expf(m0 - nm) + __expf(v.x - nm); m0 = nm;
          if (v.x > a0) { a0 = v.x; i0 = 4 * i4 + 0; } }
        { float nm = fmaxf(m1, v.y); s1 = s1 * __expf(m1 - nm) + __expf(v.y - nm); m1 = nm;
          if (v.y > a1) { a1 = v.y; i1 = 4 * i4 + 1; } }
        { float nm = fmaxf(m2, v.z); s2 = s2 * __expf(m2 - nm) + __expf(v.z - nm); m2 = nm;
          if (v.z > a2) { a2 = v.z; i2 = 4 * i4 + 2; } }
        { float nm = fmaxf(m3, v.w); s3 = s3 * __expf(m3 - nm) + __expf(v.w - nm); m3 = nm;
          if (v.w > a3) { a3 = v.w; i3 = 4 * i4 + 3; } }
    }
    m = m0; s = s0; av = a0; ai = i0;
    comb(m, s, av, ai, m1, s1, a1, i1);
    comb(m, s, av, ai, m2, s2, a2, i2);
    comb(m, s, av, ai, m3, s3, a3, i3);
}

// Block-wide reduce; valid result in (warp 0, lane 0).
__device__ __forceinline__ void block_reduce(float& m, float& s, float& av, int& ai,
                                             float* sm, float* ss, float* sav, int* sai) {
    #pragma unroll
    for (int off = 16; off > 0; off >>= 1) {
        float m2  = __shfl_down_sync(0xffffffffu, m,  off);
        float s2  = __shfl_down_sync(0xffffffffu, s,  off);
        float av2 = __shfl_down_sync(0xffffffffu, av, off);
        int   ai2 = __shfl_down_sync(0xffffffffu, ai, off);
        comb(m, s, av, ai, m2, s2, av2, ai2);
    }
    const int lane = threadIdx.x & 31;
    const int warp = threadIdx.x >> 5;
    if (lane == 0) { sm[warp] = m; ss[warp] = s; sav[warp] = av; sai[warp] = ai; }
    __syncthreads();
    if (warp == 0) {
        if (lane < 8) { m = sm[lane]; s = ss[lane]; av = sav[lane]; ai = sai[lane]; }
        else          { m = -FLT_MAX; s = 0.f; av = -FLT_MAX; ai = 0x7fffffff; }
        #pragma unroll
        for (int off = 4; off > 0; off >>= 1) {
            float m2  = __shfl_down_sync(0xffffffffu, m,  off);
            float s2  = __shfl_down_sync(0xffffffffu, s,  off);
            float av2 = __shfl_down_sync(0xffffffffu, av, off);
            int   ai2 = __shfl_down_sync(0xffffffffu, ai, off);
            comb(m, s, av, ai, m2, s2, av2, ai2);
        }
    }
}

__global__ void __launch_bounds__(256) fused_taxanet_kernel(
    const float* __restrict__ y_pred,
    const int*   __restrict__ y_true,
    const float* __restrict__ H,
    float*       __restrict__ out)
{
    const int b   = blockIdx.x;
    const int tid = threadIdx.x;

    __shared__ float sm[8], ss[8], sav[8];
    __shared__ int   sai[8];
    __shared__ int   s_g[4];
    __shared__ float s_nll[4];
    __shared__ unsigned s_old;

    const int sizes[4] = {100, 400, 2000, 8000};

    // Big level first: front-loads the bulk DRAM reads.
    #pragma unroll
    for (int jj = 0; jj < 4; jj++) {
        const int j = 3 - jj;
        const int n = sizes[j];
        const float* row = y_pred + ((size_t)b * NLEV + j) * CDIM;

        float m, s, av; int ai;
        accum_level(reinterpret_cast<const float4*>(row), n >> 2, m, s, av, ai);
        block_reduce(m, s, av, ai, sm, ss, sav, sai);

        if (tid == 0) {
            s_g[j] = ai;
            if (j > 0) {
                int tgt = y_true[b * NLEV + j];
                tgt = min(max(tgt, 0), n - 1);   // defensive; correct targets in-range
                s_nll[j] = m + logf(s) - __ldg(&row[tgt]);
            }
        }
        __syncthreads();
    }

    if (tid == 0) {
        const int g0 = s_g[0];
        const int g1 = s_g[1] + 100;
        const int g2 = s_g[2] + 500;
        const int g3 = s_g[3] + 2500;

        const float E    = 2.7182817459106445f;   // float32(np.e)
        const float invB = 1.0f / (float)BATCH;

        float c01 = (__ldg(&H[(size_t)g0 * NTOTAL + g1]) == 1.0f) ? 1.0f : 0.0f;
        float c12 = (__ldg(&H[(size_t)g1 * NTOTAL + g2]) == 1.0f) ? 1.0f : 0.0f;
        float c23 = (__ldg(&H[(size_t)g2 * NTOTAL + g3]) == 1.0f) ? 1.0f : 0.0f;

        float p = 0.25f * (E * c01 + s_nll[1] * invB)
                + 0.15f * (E * c12 + s_nll[2] * invB)
                + 0.10f * (E * c23 + s_nll[3] * invB);

        g_part[b] = p;
        __threadfence();
        s_old = atomicAdd(&g_count, 1u);
    }
    __syncthreads();

    // Last block to arrive performs the deterministic final reduction.
    if (s_old == BATCH - 1) {
        volatile float* vp = g_part;
        float v = vp[tid];
        __shared__ float red[256];
        red[tid] = v;
        __syncthreads();
        #pragma unroll
        for (int off = 128; off > 0; off >>= 1) {
            if (tid < off) red[tid] += red[tid + off];
            __syncthreads();
        }
        if (tid == 0) {
            out[0] = red[0];
            g_count = 0;   // reset for next (graph-replayed) launch
        }
    }
}

extern "C" void kernel_launch(void* const* d_in, const int* in_sizes, int n_in,
                              void* d_out, int out_size) {
    const float* y_pred = (const float*)d_in[0];
    const int*   y_true = (const int*)d_in[1];
    const float* H      = (const float*)d_in[2];
    float*       out    = (float*)d_out;

    fused_taxanet_kernel<<<BATCH, 256>>>(y_pred, y_true, H, out);
}

// round 4
// speedup vs baseline: 1.3721x; 1.1599x over previous
#include <cuda_runtime.h>
#include <math.h>
#include <float.h>

#define BATCH   256
#define NLEV    4
#define CDIM    8000
#define NTOTAL  10500
#define THREADS 512

// Scratch (allocation-free): per-block partial + completion counter.
__device__ float        g_part[BATCH];
__device__ unsigned int g_count = 0;

__device__ __forceinline__ void amax_comb(float& av, int& ai, float av2, int ai2) {
    // larger value wins; tie -> smaller index (jnp.argmax first-max)
    if (av2 > av || (av2 == av && ai2 < ai)) { av = av2; ai = ai2; }
}

// Direct exp-sum + argmax over a level prefix. Compile-time stride/size so the
// load batch is fully unrolled (all LDG.128 issued before any math).
template<int N4, int STRIDE>
__device__ __forceinline__ void accum(const float4* __restrict__ row4, int lt,
                                      float& s, float& av, int& ai) {
    constexpr int ITERS = (N4 + STRIDE - 1) / STRIDE;
    float4 v[ITERS];
    #pragma unroll
    for (int k = 0; k < ITERS; k++) {
        int idx = lt + k * STRIDE;
        if (idx < N4) v[k] = __ldg(&row4[idx]);
        else          v[k] = make_float4(-FLT_MAX, -FLT_MAX, -FLT_MAX, -FLT_MAX);
    }
    float s0 = 0.f, s1 = 0.f, s2 = 0.f, s3 = 0.f;
    float a0 = -FLT_MAX, a1 = -FLT_MAX, a2 = -FLT_MAX, a3 = -FLT_MAX;
    int   i0 = 0x7fffffff, i1 = 0x7fffffff, i2 = 0x7fffffff, i3 = 0x7fffffff;
    #pragma unroll
    for (int k = 0; k < ITERS; k++) {
        int base = 4 * (lt + k * STRIDE);
        s0 += __expf(v[k].x); if (v[k].x > a0) { a0 = v[k].x; i0 = base + 0; }
        s1 += __expf(v[k].y); if (v[k].y > a1) { a1 = v[k].y; i1 = base + 1; }
        s2 += __expf(v[k].z); if (v[k].z > a2) { a2 = v[k].z; i2 = base + 2; }
        s3 += __expf(v[k].w); if (v[k].w > a3) { a3 = v[k].w; i3 = base + 3; }
    }
    s = (s0 + s1) + (s2 + s3);
    av = a0; ai = i0;
    amax_comb(av, ai, a1, i1);
    amax_comb(av, ai, a2, i2);
    amax_comb(av, ai, a3, i3);
}

__global__ void __launch_bounds__(THREADS, 2) fused_taxanet_kernel(
    const float* __restrict__ y_pred,
    const int*   __restrict__ y_true,
    const float* __restrict__ H,
    float*       __restrict__ out)
{
    const int b    = blockIdx.x;
    const int tid  = threadIdx.x;
    const int warp = tid >> 5;
    const int lane = tid & 31;

    __shared__ float    s_s[16], s_av[16];
    __shared__ int      s_ai[16];
    __shared__ float    s_tlogit[4];
    __shared__ int      s_g[4];
    __shared__ float    s_nll[4];
    __shared__ unsigned s_old;

    // Prefetch target logits early (L0 segment has almost no work).
    if (warp == 15 && lane < 3) {
        const int jj   = lane + 1;
        const int szs  = (jj == 1) ? 400 : (jj == 2) ? 2000 : 8000;
        int tgt = y_true[b * NLEV + jj];
        tgt = min(max(tgt, 0), szs - 1);
        s_tlogit[jj] = __ldg(&y_pred[((size_t)b * NLEV + jj) * CDIM + tgt]);
    }

    // Warp->level segments (power-of-2 sizes): [0,8)->L3 [8,12)->L2 [12,14)->L1 [14,16)->L0
    int j, seg_base;
    if (warp < 8)       { j = 3; seg_base = 0;  }
    else if (warp < 12) { j = 2; seg_base = 8;  }
    else if (warp < 14) { j = 1; seg_base = 12; }
    else                { j = 0; seg_base = 14; }
    const int lt = tid - seg_base * 32;

    const float4* row4 =
        reinterpret_cast<const float4*>(y_pred + ((size_t)b * NLEV + j) * CDIM);

    float s, av; int ai;
    if (j == 3)      accum<2000, 256>(row4, lt, s, av, ai);
    else if (j == 2) accum< 500, 128>(row4, lt, s, av, ai);
    else if (j == 1) accum< 100,  64>(row4, lt, s, av, ai);
    else             accum<  25,  64>(row4, lt, s, av, ai);

    // Warp reduce: sum + argmax
    #pragma unroll
    for (int off = 16; off > 0; off >>= 1) {
        float s2  = __shfl_down_sync(0xffffffffu, s,  off);
        float av2 = __shfl_down_sync(0xffffffffu, av, off);
        int   ai2 = __shfl_down_sync(0xffffffffu, ai, off);
        s += s2;
        amax_comb(av, ai, av2, ai2);
    }
    if (lane == 0) { s_s[warp] = s; s_av[warp] = av; s_ai[warp] = ai; }
    __syncthreads();

    // Warp 0: segmented reduce of the 16 warp partials.
    if (warp == 0) {
        float rs = 0.f, rav = -FLT_MAX; int rai = 0x7fffffff;
        if (lane < 16) { rs = s_s[lane]; rav = s_av[lane]; rai = s_ai[lane]; }
        const int segsz   = (lane < 8) ? 8 : (lane < 12) ? 4 : 2;
        const int segbase = (lane < 8) ? 0 : (lane < 12) ? 8 : (lane < 14) ? 12 : 14;
        #pragma unroll
        for (int off = 4; off > 0; off >>= 1) {
            float s2  = __shfl_down_sync(0xffffffffu, rs,  off);
            float av2 = __shfl_down_sync(0xffffffffu, rav, off);
            int   ai2 = __shfl_down_sync(0xffffffffu, rai, off);
            if (lane - segbase + off < segsz) {
                rs += s2;
                amax_comb(rav, rai, av2, ai2);
            }
        }
        // Segment heads: lane0->L3, lane8->L2, lane12->L1, lane14->L0
        if (lane == 0)       { s_g[3] = rai; s_nll[3] = logf(rs) - s_tlogit[3]; }
        else if (lane == 8)  { s_g[2] = rai; s_nll[2] = logf(rs) - s_tlogit[2]; }
        else if (lane == 12) { s_g[1] = rai; s_nll[1] = logf(rs) - s_tlogit[1]; }
        else if (lane == 14) { s_g[0] = rai; }
    }
    __syncthreads();

    if (tid == 0) {
        const int g0 = s_g[0];
        const int g1 = s_g[1] + 100;
        const int g2 = s_g[2] + 500;
        const int g3 = s_g[3] + 2500;

        const float E    = 2.7182817459106445f;   // float32(np.e)
        const float invB = 1.0f / (float)BATCH;

        float h01 = __ldg(&H[(size_t)g0 * NTOTAL + g1]);
        float h12 = __ldg(&H[(size_t)g1 * NTOTAL + g2]);
        float h23 = __ldg(&H[(size_t)g2 * NTOTAL + g3]);
        float c01 = (h01 == 1.0f) ? 1.0f : 0.0f;
        float c12 = (h12 == 1.0f) ? 1.0f : 0.0f;
        float c23 = (h23 == 1.0f) ? 1.0f : 0.0f;

        float p = 0.25f * (E * c01 + s_nll[1] * invB)
                + 0.15f * (E * c12 + s_nll[2] * invB)
                + 0.10f * (E * c23 + s_nll[3] * invB);

        g_part[b] = p;
        __threadfence();
        s_old = atomicAdd(&g_count, 1u);
    }
    __syncthreads();

    // Last block performs the deterministic final reduction.
    if (s_old == BATCH - 1) {
        float v = 0.f;
        if (tid < BATCH) {
            volatile float* vp = g_part;
            v = vp[tid];
        }
        __shared__ float red[256];
        if (tid < 256) red[tid] = v;
        __syncthreads();
        #pragma unroll
        for (int off = 128; off > 0; off >>= 1) {
            if (tid < off) red[tid] += red[tid + off];
            __syncthreads();
        }
        if (tid == 0) {
            out[0] = red[0];
            g_count = 0;   // reset for graph replay
        }
    }
}

extern "C" void kernel_launch(void* const* d_in, const int* in_sizes, int n_in,
                              void* d_out, int out_size) {
    const float* y_pred = (const float*)d_in[0];
    const int*   y_true = (const int*)d_in[1];
    const float* H      = (const float*)d_in[2];
    float*       out    = (float*)d_out;

    fused_taxanet_kernel<<<BATCH, THREADS>>>(y_pred, y_true, H, out);
}